// round 11
// baseline (speedup 1.0000x reference)
#include <cuda_runtime.h>
#include <cstdint>

#define BB 32
#define SS 127
#define HDIM 256
#define DD 64
#define M_ROWS (BB*SS)          // 4064 = 127 * 32
#define SCALE 0.125f

// -------- scratch (static device globals; allocation is forbidden) --------
__device__ float g_qp[M_ROWS*HDIM];
__device__ float g_kp[M_ROWS*HDIM];
__device__ float g_vp[M_ROWS*HDIM];
__device__ float g_x [M_ROWS*HDIM];

// float -> tf32 (round to nearest, keep in 32-bit reg for mma)
__device__ __forceinline__ uint32_t f2tf(float f) {
    uint32_t u;
    asm("cvt.rna.tf32.f32 %0, %1;" : "=r"(u) : "f"(f));
    return u;
}

__device__ __forceinline__ void cpasync16(uint32_t s_addr, const void* gptr) {
    asm volatile("cp.async.ca.shared.global [%0], [%1], 16;"
                 :: "r"(s_addr), "l"(gptr));
}
__device__ __forceinline__ void cpasync_commit() {
    asm volatile("cp.async.commit_group;");
}
template <int N>
__device__ __forceinline__ void cpasync_wait() {
    asm volatile("cp.async.wait_group %0;" :: "n"(N));
}

// ---------------------------------------------------------------------------
// tf32 GEMM body v5: C[M,256] = A[M,256] @ W[256,256]^T + bias
// BM=128 (guarded vs M=4064), BN=128, BK=16, 256 threads.
// 8 warps in 2(m) x 4(n) grid, warp tile 64x32 (mfrag=4 x nfrag=4).
// Double-buffered cp.async; tf32 convert at fragment load.
// Smem row stride 20 (gid*20 mod 32 = {0,20,8,28,16,4,24,12}: conflict-free).
// Static smem 40 KB. W re-read cut 127x -> 32x vs v4.
// ---------------------------------------------------------------------------
__device__ __forceinline__ void gemm_body(const float* __restrict__ A,
                                          const float* __restrict__ W,
                                          const float* __restrict__ bias,
                                          float* __restrict__ C)
{
    __shared__ float As[2][128][20];   // 20 KB
    __shared__ float Bs[2][128][20];   // 20 KB

    const int t     = threadIdx.x;
    const int lane  = t & 31;
    const int warp  = t >> 5;
    const int m0    = blockIdx.x * 128;
    const int n0    = blockIdx.y * 128;

    const int wm    = warp >> 2;      // 0..1
    const int wn    = warp & 3;       // 0..3
    const int mBase = wm * 64;
    const int nBase = wn * 32;
    const int gid   = lane >> 2;      // 0..7
    const int tig   = lane & 3;       // 0..3

    float acc[4][4][4];
    #pragma unroll
    for (int mf = 0; mf < 4; mf++)
        #pragma unroll
        for (int nt = 0; nt < 4; nt++)
            #pragma unroll
            for (int r = 0; r < 4; r++) acc[mf][nt][r] = 0.0f;

    const int fr = t >> 2;            // 0..63 (fill row base)
    const int fc = (t & 3) * 4;       // 0,4,8,12

    // prefetch stage kt (k0 = kt*16) into buffer buf
    auto prefetch = [&](int kt, int buf) {
        const int k0 = kt * 16;
        #pragma unroll
        for (int i = 0; i < 2; i++) {
            int m = m0 + fr + i * 64;
            if (m > M_ROWS - 1) m = M_ROWS - 1;      // clamp (dup load, store-guarded)
            uint32_t dst = (uint32_t)__cvta_generic_to_shared(&As[buf][fr + i * 64][fc]);
            cpasync16(dst, &A[(size_t)m * 256 + k0 + fc]);
        }
        #pragma unroll
        for (int i = 0; i < 2; i++) {
            uint32_t dst = (uint32_t)__cvta_generic_to_shared(&Bs[buf][fr + i * 64][fc]);
            cpasync16(dst, &W[(size_t)(n0 + fr + i * 64) * 256 + k0 + fc]);
        }
        cpasync_commit();
    };

    prefetch(0, 0);

    for (int kt = 0; kt < 16; kt++) {
        const int cur = kt & 1;
        if (kt + 1 < 16) {
            prefetch(kt + 1, cur ^ 1);
            cpasync_wait<1>();
        } else {
            cpasync_wait<0>();
        }
        __syncthreads();

        #pragma unroll
        for (int s = 0; s < 2; s++) {
            uint32_t a[4][4];
            #pragma unroll
            for (int mf = 0; mf < 4; mf++) {
                a[mf][0] = f2tf(As[cur][mBase + mf * 16 + gid    ][s * 8 + tig    ]);
                a[mf][1] = f2tf(As[cur][mBase + mf * 16 + gid + 8][s * 8 + tig    ]);
                a[mf][2] = f2tf(As[cur][mBase + mf * 16 + gid    ][s * 8 + tig + 4]);
                a[mf][3] = f2tf(As[cur][mBase + mf * 16 + gid + 8][s * 8 + tig + 4]);
            }
            #pragma unroll
            for (int nt = 0; nt < 4; nt++) {
                uint32_t b0 = f2tf(Bs[cur][nBase + nt * 8 + gid][s * 8 + tig    ]);
                uint32_t b1 = f2tf(Bs[cur][nBase + nt * 8 + gid][s * 8 + tig + 4]);
                #pragma unroll
                for (int mf = 0; mf < 4; mf++) {
                    asm volatile(
                        "mma.sync.aligned.m16n8k8.row.col.f32.tf32.tf32.f32 "
                        "{%0,%1,%2,%3}, {%4,%5,%6,%7}, {%8,%9}, {%0,%1,%2,%3};"
                        : "+f"(acc[mf][nt][0]), "+f"(acc[mf][nt][1]),
                          "+f"(acc[mf][nt][2]), "+f"(acc[mf][nt][3])
                        : "r"(a[mf][0]), "r"(a[mf][1]), "r"(a[mf][2]), "r"(a[mf][3]),
                          "r"(b0), "r"(b1));
                }
            }
        }
        __syncthreads();
    }

    #pragma unroll
    for (int mf = 0; mf < 4; mf++)
        #pragma unroll
        for (int nt = 0; nt < 4; nt++) {
            int c0 = n0 + nBase + nt * 8 + tig * 2;
            int r0 = m0 + mBase + mf * 16 + gid;
            float bv0 = bias[c0], bv1 = bias[c0 + 1];
            if (r0 < M_ROWS) {
                float2 o0 = make_float2(acc[mf][nt][0] + bv0, acc[mf][nt][1] + bv1);
                *(float2*)&C[(size_t)r0 * 256 + c0] = o0;
            }
            if (r0 + 8 < M_ROWS) {
                float2 o1 = make_float2(acc[mf][nt][2] + bv0, acc[mf][nt][3] + bv1);
                *(float2*)&C[(size_t)(r0 + 8) * 256 + c0] = o1;
            }
        }
}

// QKV fused: blockIdx.z selects which projection
__global__ __launch_bounds__(256) void gemm_qkv_kernel(
    const float* __restrict__ q_in, const float* __restrict__ k_in,
    const float* __restrict__ v_in,
    const float* __restrict__ Wq, const float* __restrict__ Wk,
    const float* __restrict__ Wv,
    const float* __restrict__ bq, const float* __restrict__ bk,
    const float* __restrict__ bv)
{
    const float* A; const float* W; const float* bias; float* C;
    if (blockIdx.z == 0)      { A = q_in; W = Wq; bias = bq; C = g_qp; }
    else if (blockIdx.z == 1) { A = k_in; W = Wk; bias = bk; C = g_kp; }
    else                      { A = v_in; W = Wv; bias = bv; C = g_vp; }
    gemm_body(A, W, bias, C);
}

__global__ __launch_bounds__(256) void gemm_out_kernel(
    const float* __restrict__ Wo, const float* __restrict__ bo,
    float* __restrict__ out)
{
    gemm_body(g_x, Wo, bo, out);
}

// ---------------------------------------------------------------------------
// Attention: one block per (b,q). Exploits remove-mask sparsity:
// for q>=3 only k in {0,1,2,blk,blk+1} can be live. Masked columns contribute
// exactly 0 after softmax (exp(-1e5 - max) underflows in fp32) unless ALL
// columns are masked, in which case attn is uniform 1/S (fallback path).
// Score identity: score = (q_h + eq) . (k_h + ek) * SCALE  (4 einsums fused).
// ---------------------------------------------------------------------------
__global__ __launch_bounds__(128) void attn_kernel(
    const int*   __restrict__ graph,
    const float* __restrict__ e_key,
    const float* __restrict__ e_val,
    const float* __restrict__ e_qry)
{
    const int bid  = blockIdx.x;
    const int b    = bid / SS;
    const int q    = bid - b * SS;
    const int t    = threadIdx.x;
    const int lane = t & 31;
    const int w    = t >> 5;

    __shared__ float s_q[256];
    __shared__ int   s_list[128];
    __shared__ float s_sc[4][128];
    __shared__ int   s_wcnt[4];

    const int row = bid;                 // b*S + q
    s_q[t]       = g_qp[(size_t)row * 256 + t];
    s_q[t + 128] = g_qp[(size_t)row * 256 + 128 + t];

    // ---- build live-k list (ballot compaction) ----
    bool keep = false;
    const int k = t;
    if (k < SS) {
        bool rm;
        if (q < 3 || k < 3) rm = true;
        else {
            int blk = 3 + 2 * ((q - 3) >> 1);
            rm = (k >= blk) && (k < blk + 2);
        }
        if (rm) keep = (graph[((size_t)b * SS + q) * SS + k] != 0);
    }
    unsigned bal = __ballot_sync(0xFFFFFFFFu, keep);
    if (lane == 0) s_wcnt[w] = __popc(bal);
    __syncthreads();
    int base = 0;
    #pragma unroll
    for (int i = 0; i < 4; i++) base += (i < w) ? s_wcnt[i] : 0;
    const int total = s_wcnt[0] + s_wcnt[1] + s_wcnt[2] + s_wcnt[3];
    if (keep)
        s_list[base + __popc(bal & ((1u << lane) - 1))] = k;
    __syncthreads();

    // ---- scores: one warp per live k, all 4 heads at once (float2/lane) ----
    for (int p = w; p < total; p += 4) {
        const int kk = s_list[p];
        const float2* eqp = (const float2*)(e_qry + ((size_t)(b * SS + kk) * SS + q) * DD);
        const float2* ekp = (const float2*)(e_key + ((size_t)(b * SS + q) * SS + kk) * DD);
        const float2* kpp = (const float2*)(g_kp + (size_t)(b * SS + kk) * 256);
        float2 eq = eqp[lane];
        float2 ek = ekp[lane];
        float ps[4];
        #pragma unroll
        for (int h = 0; h < 4; h++) {
            float2 qv = *(const float2*)&s_q[h * 64 + lane * 2];
            float2 kv = kpp[h * 32 + lane];
            ps[h] = (qv.x + eq.x) * (kv.x + ek.x) + (qv.y + eq.y) * (kv.y + ek.y);
        }
        #pragma unroll
        for (int off = 16; off; off >>= 1)
            #pragma unroll
            for (int h = 0; h < 4; h++)
                ps[h] += __shfl_down_sync(0xFFFFFFFFu, ps[h], off);
        if (lane == 0)
            #pragma unroll
            for (int h = 0; h < 4; h++) s_sc[h][p] = ps[h] * SCALE;
    }
    __syncthreads();

    // ---- softmax over live set (warp w == head h) ----
    if (total > 0) {
        float m = -3.0e38f;
        for (int p = lane; p < total; p += 32) m = fmaxf(m, s_sc[w][p]);
        #pragma unroll
        for (int off = 16; off; off >>= 1)
            m = fmaxf(m, __shfl_xor_sync(0xFFFFFFFFu, m, off));
        float sum = 0.0f;
        for (int p = lane; p < total; p += 32) {
            float e = __expf(s_sc[w][p] - m);
            s_sc[w][p] = e;
            sum += e;
        }
        #pragma unroll
        for (int off = 16; off; off >>= 1)
            sum += __shfl_xor_sync(0xFFFFFFFFu, sum, off);
        float inv = 1.0f / sum;
        for (int p = lane; p < total; p += 32) s_sc[w][p] *= inv;
    }
    __syncthreads();

    // ---- output: thread t owns one float2 of the 256-wide row ----
    const int dp = t & 63;
    const int hp = t >> 6;               // 0 or 1
    const int h  = 2 * hp + (dp >> 5);
    const int dd = (dp * 2) & 63;
    float2 acc = make_float2(0.0f, 0.0f);
    const float* evbase = e_val + ((size_t)(b * SS + q) * SS) * DD;

    if (total > 0) {
        #pragma unroll 4
        for (int p = 0; p < total; p++) {
            const int kk = s_list[p];
            float2 ev = *(const float2*)&evbase[(size_t)kk * DD + dd];
            float2 vv = *(const float2*)&g_vp[(size_t)(b * SS + kk) * 256 + hp * 128 + dp * 2];
            float sc = s_sc[h][p];
            acc.x += sc * (vv.x + ev.x);
            acc.y += sc * (vv.y + ev.y);
        }
    } else {
        // all columns masked -> softmax of equal values -> uniform 1/S
        #pragma unroll 4
        for (int kk = 0; kk < SS; kk++) {
            float2 ev = *(const float2*)&evbase[(size_t)kk * DD + dd];
            float2 vv = *(const float2*)&g_vp[(size_t)(b * SS + kk) * 256 + hp * 128 + dp * 2];
            acc.x += vv.x + ev.x;
            acc.y += vv.y + ev.y;
        }
        const float invS = 1.0f / (float)SS;
        acc.x *= invS; acc.y *= invS;
    }
    *(float2*)&g_x[(size_t)row * 256 + hp * 128 + dp * 2] = acc;
}

// ---------------------------------------------------------------------------
extern "C" void kernel_launch(void* const* d_in, const int* in_sizes, int n_in,
                              void* d_out, int out_size)
{
    const float* query = (const float*)d_in[0];
    const float* key   = (const float*)d_in[1];
    const float* value = (const float*)d_in[2];
    const int*   graph = (const int*)  d_in[3];
    const float* e_key = (const float*)d_in[4];
    const float* e_val = (const float*)d_in[5];
    const float* e_qry = (const float*)d_in[6];
    const float* Wq = (const float*)d_in[7];
    const float* bq = (const float*)d_in[8];
    const float* Wk = (const float*)d_in[9];
    const float* bk = (const float*)d_in[10];
    const float* Wv = (const float*)d_in[11];
    const float* bv = (const float*)d_in[12];
    const float* Wo = (const float*)d_in[13];
    const float* bo = (const float*)d_in[14];
    float* out = (float*)d_out;

    dim3 g_qkv((M_ROWS + 127) / 128, 256 / 128, 3);
    gemm_qkv_kernel<<<g_qkv, 256>>>(query, key, value, Wq, Wk, Wv, bq, bk, bv);

    attn_kernel<<<M_ROWS, 128>>>(graph, e_key, e_val, e_qry);

    dim3 g_o((M_ROWS + 127) / 128, 256 / 128, 1);
    gemm_out_kernel<<<g_o, 256>>>(Wo, bo, out);
}